// round 4
// baseline (speedup 1.0000x reference)
#include <cuda_runtime.h>
#include <cuda_bf16.h>
#include <math_constants.h>

#define NN 50000
#define NE 800000
#define HID 64
#define FULL 0xffffffffu

// ---------------------------------------------------------------------------
// Scratch (device globals; allocation-free per harness rules)
// ---------------------------------------------------------------------------
__device__ __align__(16) float    g_m0  [NN * HID];   // n @ W1_rel[0]
__device__ __align__(16) float    g_m1  [NN * HID];   // n @ W1_rel[1]
__device__ __align__(16) float    g_r1  [NN * HID];   // n @ W1_root + b1
__device__ __align__(16) float    g_hpre[NN * HID];   // pre-relu h (conv1 out)
__device__ __align__(16) float    g_p0  [NN * HID];   // h @ W2_rel[0]
__device__ __align__(16) float    g_p1  [NN * HID];   // h @ W2_rel[1]
__device__ __align__(16) float    g_r2  [NN * HID];   // h @ W2_root + b2
// CSR by dst
__device__ int      g_deg[NN];
__device__ int      g_off[NN + 1];
__device__ int      g_cur[NN];
__device__ unsigned g_csr_pk[NE];                       // src | (typ<<31)
__device__ __align__(16) uint4 g_csr_ed[NE];            // {pk, ea.x, ea.y, 0}

// ---------------------------------------------------------------------------
// CSR build: histogram, block-wide scan (1 block), fill
// ---------------------------------------------------------------------------
__global__ void k_hist(const int* __restrict__ ei) {
    int e = blockIdx.x * blockDim.x + threadIdx.x;
    if (e < NE) atomicAdd(&g_deg[ei[NE + e]], 1);
}

__global__ void k_scan() {
    __shared__ int warpsum[32];
    int tid  = threadIdx.x;
    int lane = tid & 31;
    int wid  = tid >> 5;
    int carry = 0;
    for (int base = 0; base < NN; base += 1024) {
        int i = base + tid;
        int v = (i < NN) ? g_deg[i] : 0;
        int s = v;
        #pragma unroll
        for (int o = 1; o < 32; o <<= 1) {
            int t = __shfl_up_sync(FULL, s, o);
            if (lane >= o) s += t;
        }
        if (lane == 31) warpsum[wid] = s;
        __syncthreads();
        if (wid == 0) {
            int ws = warpsum[lane];
            #pragma unroll
            for (int o = 1; o < 32; o <<= 1) {
                int t = __shfl_up_sync(FULL, ws, o);
                if (lane >= o) ws += t;
            }
            warpsum[lane] = ws;
        }
        __syncthreads();
        int wpre = (wid > 0) ? warpsum[wid - 1] : 0;
        int excl = carry + wpre + s - v;
        if (i < NN) { g_off[i] = excl; g_cur[i] = excl; }
        int total = warpsum[31];
        __syncthreads();
        carry += total;
    }
    if (tid == 0) g_off[NN] = NE;
}

__global__ void k_fill(const int* __restrict__ ei,
                       const float* __restrict__ ea,
                       const int* __restrict__ et) {
    int e = blockIdx.x * blockDim.x + threadIdx.x;
    if (e >= NE) return;
    int dst = ei[NE + e];
    int pos = atomicAdd(&g_cur[dst], 1);
    unsigned pk = (unsigned)ei[e] | ((unsigned)et[e] << 31);
    float2 a = ((const float2*)ea)[e];
    g_csr_pk[pos] = pk;
    g_csr_ed[pos] = make_uint4(pk, __float_as_uint(a.x), __float_as_uint(a.y), 0u);
}

// ---------------------------------------------------------------------------
// Persistent fused triple GEMM (round-2 FFMA datapath):
//   out{0,1,2}[N,64] = f(in)[N,64] @ {W0,W1,W2}  (+bias on W2)
// mode 0: f(in) = relu(x@Wn+bn) fused;  mode 1: f(in) = relu(in)
// grid = 444 (3 blocks/SM), weights loaded ONCE per block, stride loop over tiles.
// ---------------------------------------------------------------------------
#define NPB 64
#define INPAD 68
#define NTILES ((NN + NPB - 1) / NPB)
extern __shared__ float s_dyn[];
__global__ __launch_bounds__(256)
void k_gemm3(const float* __restrict__ in,
             const float* __restrict__ W0,
             const float* __restrict__ W1,
             const float* __restrict__ W2,
             const float* __restrict__ bias2,
             const float* __restrict__ Wn,
             const float* __restrict__ bn,
             float* __restrict__ o0,
             float* __restrict__ o1,
             float* __restrict__ o2,
             int mode) {
    float* sW  = s_dyn;                 // 3 * 64 * 64
    float* sIn = s_dyn + 3 * 4096;      // 64 * INPAD
    __shared__ float sX[NPB * 3];
    int tid = threadIdx.x;

    for (int i = tid * 4; i < 4096; i += 1024) {
        *(float4*)&sW[i]        = *(const float4*)&W0[i];
        *(float4*)&sW[4096 + i] = *(const float4*)&W1[i];
        *(float4*)&sW[8192 + i] = *(const float4*)&W2[i];
    }

    int tx = tid & 15, ty = tid >> 4;
    int c0 = tx * 4, n0 = ty * 4;
    float4 bv = *(const float4*)&bias2[c0];

    for (int tile = blockIdx.x; tile < NTILES; tile += gridDim.x) {
        int nbase = tile * NPB;
        __syncthreads();   // protect sIn from previous iteration's readers

        if (mode == 0) {
            if (tid < NPB * 3) {
                int nd = tid / 3, c = tid % 3;
                int node = nbase + nd;
                sX[tid] = (node < NN) ? __ldg(&in[node * 3 + c]) : 0.f;
            }
            __syncthreads();
            for (int i = tid; i < NPB * 64; i += 256) {
                int nd = i >> 6, k = i & 63;
                float v = fmaf(sX[nd * 3 + 0], __ldg(&Wn[k]),
                          fmaf(sX[nd * 3 + 1], __ldg(&Wn[64 + k]),
                          fmaf(sX[nd * 3 + 2], __ldg(&Wn[128 + k]), __ldg(&bn[k]))));
                sIn[nd * INPAD + k] = fmaxf(v, 0.f);
            }
        } else {
            for (int i = tid * 4; i < NPB * 64; i += 1024) {
                int nd = i >> 6, k = i & 63;
                int node = nbase + nd;
                float4 v = make_float4(0.f, 0.f, 0.f, 0.f);
                if (node < NN) v = *(const float4*)&in[node * 64 + k];
                v.x = fmaxf(v.x, 0.f); v.y = fmaxf(v.y, 0.f);
                v.z = fmaxf(v.z, 0.f); v.w = fmaxf(v.w, 0.f);
                *(float4*)&sIn[nd * INPAD + k] = v;
            }
        }
        __syncthreads();

        float acc[3][4][4] = {};

        #pragma unroll 2
        for (int k = 0; k < 64; k++) {
            float4 w0 = *(float4*)&sW[k * 64 + c0];
            float4 w1 = *(float4*)&sW[4096 + k * 64 + c0];
            float4 w2 = *(float4*)&sW[8192 + k * 64 + c0];
            float a[4];
            #pragma unroll
            for (int j = 0; j < 4; j++) a[j] = sIn[(n0 + j) * INPAD + k];
            #pragma unroll
            for (int j = 0; j < 4; j++) {
                acc[0][j][0] = fmaf(a[j], w0.x, acc[0][j][0]);
                acc[0][j][1] = fmaf(a[j], w0.y, acc[0][j][1]);
                acc[0][j][2] = fmaf(a[j], w0.z, acc[0][j][2]);
                acc[0][j][3] = fmaf(a[j], w0.w, acc[0][j][3]);
                acc[1][j][0] = fmaf(a[j], w1.x, acc[1][j][0]);
                acc[1][j][1] = fmaf(a[j], w1.y, acc[1][j][1]);
                acc[1][j][2] = fmaf(a[j], w1.z, acc[1][j][2]);
                acc[1][j][3] = fmaf(a[j], w1.w, acc[1][j][3]);
                acc[2][j][0] = fmaf(a[j], w2.x, acc[2][j][0]);
                acc[2][j][1] = fmaf(a[j], w2.y, acc[2][j][1]);
                acc[2][j][2] = fmaf(a[j], w2.z, acc[2][j][2]);
                acc[2][j][3] = fmaf(a[j], w2.w, acc[2][j][3]);
            }
        }

        #pragma unroll
        for (int j = 0; j < 4; j++) {
            int node = nbase + n0 + j;
            if (node >= NN) break;
            *(float4*)&o0[node * 64 + c0] =
                make_float4(acc[0][j][0], acc[0][j][1], acc[0][j][2], acc[0][j][3]);
            *(float4*)&o1[node * 64 + c0] =
                make_float4(acc[1][j][0], acc[1][j][1], acc[1][j][2], acc[1][j][3]);
            *(float4*)&o2[node * 64 + c0] =
                make_float4(acc[2][j][0] + bv.x, acc[2][j][1] + bv.y,
                            acc[2][j][2] + bv.z, acc[2][j][3] + bv.w);
        }
    }
}

// ---------------------------------------------------------------------------
// conv1 gather: one warp per dst node; 4-edge unroll (MLP=4).
//   msum  = sum_e m_{typ}[src]          (lane owns cols 2l, 2l+1)
//   aggev = sum_e relu(ea@We+be)        (lane owns dim l of 32)
//   hpre  = r1 + msum + aggev @ W1_edge
// ---------------------------------------------------------------------------
__global__ void k_gather1(const float* __restrict__ We,
                          const float* __restrict__ be,
                          const float* __restrict__ W1e) {
    __shared__ float  sWe0[32], sWe1[32], sbe[32];
    __shared__ float2 sW1e[32 * 32];
    int tid = threadIdx.x;
    if (tid < 32) { sWe0[tid] = We[tid]; sWe1[tid] = We[32 + tid]; sbe[tid] = be[tid]; }
    for (int i = tid; i < 1024; i += blockDim.x)
        sW1e[i] = ((const float2*)W1e)[i];
    __syncthreads();

    int lane = tid & 31;
    int node = (blockIdx.x * blockDim.x + tid) >> 5;
    if (node >= NN) return;
    int s0 = g_off[node], s1 = g_off[node + 1];

    float  ev = 0.f;
    float2 ms = make_float2(0.f, 0.f);
    int e = s0;
    for (; e + 4 <= s1; e += 4) {
        uint4 d0 = __ldg(&g_csr_ed[e]);
        uint4 d1 = __ldg(&g_csr_ed[e + 1]);
        uint4 d2 = __ldg(&g_csr_ed[e + 2]);
        uint4 d3 = __ldg(&g_csr_ed[e + 3]);
        const float2* t0 = (d0.x >> 31) ? (const float2*)g_m1 : (const float2*)g_m0;
        const float2* t1 = (d1.x >> 31) ? (const float2*)g_m1 : (const float2*)g_m0;
        const float2* t2 = (d2.x >> 31) ? (const float2*)g_m1 : (const float2*)g_m0;
        const float2* t3 = (d3.x >> 31) ? (const float2*)g_m1 : (const float2*)g_m0;
        float2 v0 = __ldg(&t0[(d0.x & 0x7FFFFFFFu) * 32 + lane]);
        float2 v1 = __ldg(&t1[(d1.x & 0x7FFFFFFFu) * 32 + lane]);
        float2 v2 = __ldg(&t2[(d2.x & 0x7FFFFFFFu) * 32 + lane]);
        float2 v3 = __ldg(&t3[(d3.x & 0x7FFFFFFFu) * 32 + lane]);
        ev += fmaxf(fmaf(__uint_as_float(d0.y), sWe0[lane],
                    fmaf(__uint_as_float(d0.z), sWe1[lane], sbe[lane])), 0.f);
        ev += fmaxf(fmaf(__uint_as_float(d1.y), sWe0[lane],
                    fmaf(__uint_as_float(d1.z), sWe1[lane], sbe[lane])), 0.f);
        ev += fmaxf(fmaf(__uint_as_float(d2.y), sWe0[lane],
                    fmaf(__uint_as_float(d2.z), sWe1[lane], sbe[lane])), 0.f);
        ev += fmaxf(fmaf(__uint_as_float(d3.y), sWe0[lane],
                    fmaf(__uint_as_float(d3.z), sWe1[lane], sbe[lane])), 0.f);
        ms.x += (v0.x + v1.x) + (v2.x + v3.x);
        ms.y += (v0.y + v1.y) + (v2.y + v3.y);
    }
    for (; e < s1; e++) {
        uint4 d = __ldg(&g_csr_ed[e]);
        ev += fmaxf(fmaf(__uint_as_float(d.y), sWe0[lane],
                    fmaf(__uint_as_float(d.z), sWe1[lane], sbe[lane])), 0.f);
        const float2* m = (d.x >> 31) ? (const float2*)g_m1 : (const float2*)g_m0;
        float2 v = __ldg(&m[(d.x & 0x7FFFFFFFu) * 32 + lane]);
        ms.x += v.x; ms.y += v.y;
    }

    float2 acc = make_float2(0.f, 0.f);
    #pragma unroll
    for (int k = 0; k < 32; k++) {
        float ek = __shfl_sync(FULL, ev, k);
        float2 w = sW1e[k * 32 + lane];
        acc.x = fmaf(ek, w.x, acc.x);
        acc.y = fmaf(ek, w.y, acc.y);
    }
    float2 r = *(const float2*)&g_r1[node * 64 + 2 * lane];
    *(float2*)&g_hpre[node * 64 + 2 * lane] =
        make_float2(r.x + ms.x + acc.x, r.y + ms.y + acc.y);
}

// ---------------------------------------------------------------------------
// conv2 gather + readout: one warp per dst node; 4-edge unroll.
//   mx = max_e p_{typ}[src] (0 for empty); h2 = relu(mx + r2)
//   out = tanh(h2 @ Wc + bc) * 5
// ---------------------------------------------------------------------------
__global__ void k_gather2(const float* __restrict__ Wc,
                          const float* __restrict__ bc,
                          float* __restrict__ out) {
    int tid  = threadIdx.x;
    int lane = tid & 31;
    int node = (blockIdx.x * blockDim.x + tid) >> 5;
    if (node >= NN) return;
    int s0 = g_off[node], s1 = g_off[node + 1];

    float2 mx = make_float2(-CUDART_INF_F, -CUDART_INF_F);
    int e = s0;
    for (; e + 4 <= s1; e += 4) {
        unsigned k0 = __ldg(&g_csr_pk[e]);
        unsigned k1 = __ldg(&g_csr_pk[e + 1]);
        unsigned k2 = __ldg(&g_csr_pk[e + 2]);
        unsigned k3 = __ldg(&g_csr_pk[e + 3]);
        const float2* t0 = (k0 >> 31) ? (const float2*)g_p1 : (const float2*)g_p0;
        const float2* t1 = (k1 >> 31) ? (const float2*)g_p1 : (const float2*)g_p0;
        const float2* t2 = (k2 >> 31) ? (const float2*)g_p1 : (const float2*)g_p0;
        const float2* t3 = (k3 >> 31) ? (const float2*)g_p1 : (const float2*)g_p0;
        float2 v0 = __ldg(&t0[(k0 & 0x7FFFFFFFu) * 32 + lane]);
        float2 v1 = __ldg(&t1[(k1 & 0x7FFFFFFFu) * 32 + lane]);
        float2 v2 = __ldg(&t2[(k2 & 0x7FFFFFFFu) * 32 + lane]);
        float2 v3 = __ldg(&t3[(k3 & 0x7FFFFFFFu) * 32 + lane]);
        mx.x = fmaxf(mx.x, fmaxf(fmaxf(v0.x, v1.x), fmaxf(v2.x, v3.x)));
        mx.y = fmaxf(mx.y, fmaxf(fmaxf(v0.y, v1.y), fmaxf(v2.y, v3.y)));
    }
    for (; e < s1; e++) {
        unsigned pk = __ldg(&g_csr_pk[e]);
        const float2* p = (pk >> 31) ? (const float2*)g_p1 : (const float2*)g_p0;
        float2 v = __ldg(&p[(pk & 0x7FFFFFFFu) * 32 + lane]);
        mx.x = fmaxf(mx.x, v.x);
        mx.y = fmaxf(mx.y, v.y);
    }
    if (s1 == s0) mx = make_float2(0.f, 0.f);

    float2 r = *(const float2*)&g_r2[node * 64 + 2 * lane];
    float h0 = fmaxf(mx.x + r.x, 0.f);
    float h1 = fmaxf(mx.y + r.y, 0.f);
    float p = fmaf(h0, __ldg(&Wc[2 * lane]), h1 * __ldg(&Wc[2 * lane + 1]));
    #pragma unroll
    for (int o = 16; o > 0; o >>= 1) p += __shfl_xor_sync(FULL, p, o);
    if (lane == 0) out[node] = tanhf(p + __ldg(bc)) * 5.0f;
}

// ---------------------------------------------------------------------------
// launch
// ---------------------------------------------------------------------------
extern "C" void kernel_launch(void* const* d_in, const int* in_sizes, int n_in,
                              void* d_out, int out_size) {
    const float* x      = (const float*)d_in[0];
    const int*   ei     = (const int*)  d_in[1];
    const float* ea     = (const float*)d_in[2];
    const int*   et     = (const int*)  d_in[3];
    const float* Wn     = (const float*)d_in[4];
    const float* bn     = (const float*)d_in[5];
    const float* We     = (const float*)d_in[6];
    const float* be     = (const float*)d_in[7];
    const float* W1_rel = (const float*)d_in[8];
    const float* W1_edge= (const float*)d_in[9];
    const float* W1_root= (const float*)d_in[10];
    const float* b1     = (const float*)d_in[11];
    const float* W2_rel = (const float*)d_in[12];
    const float* W2_root= (const float*)d_in[13];
    const float* b2     = (const float*)d_in[14];
    const float* Wc     = (const float*)d_in[15];
    const float* bc     = (const float*)d_in[16];
    float* out          = (float*)d_out;

    float *pm0, *pm1, *pr1, *phpre, *pp0, *pp1, *pr2;
    int* pdeg;
    cudaGetSymbolAddress((void**)&pm0,   g_m0);
    cudaGetSymbolAddress((void**)&pm1,   g_m1);
    cudaGetSymbolAddress((void**)&pr1,   g_r1);
    cudaGetSymbolAddress((void**)&phpre, g_hpre);
    cudaGetSymbolAddress((void**)&pp0,   g_p0);
    cudaGetSymbolAddress((void**)&pp1,   g_p1);
    cudaGetSymbolAddress((void**)&pr2,   g_r2);
    cudaGetSymbolAddress((void**)&pdeg,  g_deg);

    static const int SMEM = (3 * 4096 + NPB * INPAD) * sizeof(float);
    cudaFuncSetAttribute(k_gemm3, cudaFuncAttributeMaxDynamicSharedMemorySize, SMEM);

    const int gemmGrid  = 444;                 // 148 SMs x 3 blocks (persistent)
    const int edgeBlocks = (NE + 255) / 256;
    const int nodeWarpBlocks = (NN * 32 + 255) / 256;

    // CSR build (shared by both convs)
    cudaMemsetAsync(pdeg, 0, NN * sizeof(int));
    k_hist<<<edgeBlocks, 256>>>(ei);
    k_scan<<<1, 1024>>>();
    k_fill<<<edgeBlocks, 256>>>(ei, ea, et);

    // conv1 node-side: n = relu(x@Wn+bn) fused; m0, m1, r1
    k_gemm3<<<gemmGrid, 256, SMEM>>>(x, W1_rel, W1_rel + 4096, W1_root, b1,
                                     Wn, bn, pm0, pm1, pr1, 0);
    // conv1 gather (sum) + edge-feature fold
    k_gather1<<<nodeWarpBlocks, 256>>>(We, be, W1_edge);

    // conv2 node-side: h = relu(hpre) fused; p0, p1, r2
    k_gemm3<<<gemmGrid, 256, SMEM>>>(phpre, W2_rel, W2_rel + 4096, W2_root, b2,
                                     nullptr, nullptr, pp0, pp1, pr2, 1);
    // conv2 gather (max) + readout fused
    k_gather2<<<nodeWarpBlocks, 256>>>(Wc, bc, out);
}

// round 5
// speedup vs baseline: 1.0476x; 1.0476x over previous
#include <cuda_runtime.h>
#include <cuda_bf16.h>
#include <math_constants.h>

#define NN 50000
#define NE 800000
#define HID 64
#define FULL 0xffffffffu

// ---------------------------------------------------------------------------
// Scratch (device globals; allocation-free per harness rules)
// ---------------------------------------------------------------------------
__device__ __align__(16) float    g_m0  [NN * HID];   // n @ W1_rel[0]
__device__ __align__(16) float    g_m1  [NN * HID];   // n @ W1_rel[1]
__device__ __align__(16) float    g_r1  [NN * HID];   // n @ W1_root + b1
__device__ __align__(16) float    g_hpre[NN * HID];   // pre-relu h (conv1 out)
__device__ __align__(16) float    g_p0  [NN * HID];   // h @ W2_rel[0]
__device__ __align__(16) float    g_p1  [NN * HID];   // h @ W2_rel[1]
__device__ __align__(16) float    g_r2  [NN * HID];   // h @ W2_root + b2
// CSR by dst
__device__ int      g_deg[NN];
__device__ int      g_off[NN + 1];
__device__ int      g_cur[NN];
__device__ unsigned g_csr_pk[NE];                       // src | (typ<<31)
__device__ __align__(16) uint4 g_csr_ed[NE];            // {pk, ea.x, ea.y, 0}

// ---------------------------------------------------------------------------
// CSR build: histogram + vectorized single-block scan
// ---------------------------------------------------------------------------
__global__ void k_hist(const int* __restrict__ ei) {
    int e = blockIdx.x * blockDim.x + threadIdx.x;
    if (e < NE) atomicAdd(&g_deg[ei[NE + e]], 1);
}

// 1024 threads, 4 elements/thread/pass -> 13 passes over NN
__global__ void k_scan() {
    __shared__ int warpsum[32];
    int tid  = threadIdx.x;
    int lane = tid & 31;
    int wid  = tid >> 5;
    int carry = 0;
    for (int base = 0; base < NN; base += 4096) {
        int i0 = base + tid * 4;
        int v[4];
        #pragma unroll
        for (int j = 0; j < 4; j++) v[j] = (i0 + j < NN) ? g_deg[i0 + j] : 0;
        int tsum = (v[0] + v[1]) + (v[2] + v[3]);
        int s = tsum;
        #pragma unroll
        for (int o = 1; o < 32; o <<= 1) {
            int t = __shfl_up_sync(FULL, s, o);
            if (lane >= o) s += t;
        }
        if (lane == 31) warpsum[wid] = s;
        __syncthreads();
        if (wid == 0) {
            int ws = warpsum[lane];
            #pragma unroll
            for (int o = 1; o < 32; o <<= 1) {
                int t = __shfl_up_sync(FULL, ws, o);
                if (lane >= o) ws += t;
            }
            warpsum[lane] = ws;
        }
        __syncthreads();
        int wpre = (wid > 0) ? warpsum[wid - 1] : 0;
        int run  = carry + wpre + s - tsum;     // exclusive prefix for element 0
        #pragma unroll
        for (int j = 0; j < 4; j++) {
            if (i0 + j < NN) { g_off[i0 + j] = run; g_cur[i0 + j] = run; run += v[j]; }
        }
        int total = warpsum[31];
        __syncthreads();
        carry += total;
    }
    if (tid == 0) g_off[NN] = NE;
}

// ---------------------------------------------------------------------------
// GEMM body (round-2 datapath, verbatim):
//   out{0,1,2}[tile,64] = f(in)[tile,64] @ {W0,W1,W2}  (+bias on W2)
// mode 0: f(in) = relu(x@Wn+bn) fused;  mode 1: f(in) = relu(in)
// ---------------------------------------------------------------------------
#define NPB 64
#define INPAD 68
#define GEMM_GRID ((NN + NPB - 1) / NPB)     // 782
extern __shared__ float s_dyn[];

__device__ __forceinline__ void gemm_body(
        int gblk,
        const float* __restrict__ in,
        const float* __restrict__ W0,
        const float* __restrict__ W1,
        const float* __restrict__ W2,
        const float* __restrict__ bias2,
        const float* __restrict__ Wn,
        const float* __restrict__ bn,
        float* __restrict__ o0,
        float* __restrict__ o1,
        float* __restrict__ o2,
        int mode) {
    float* sW  = s_dyn;                 // 3 * 64 * 64
    float* sIn = s_dyn + 3 * 4096;      // 64 * INPAD
    __shared__ float sX[NPB * 3];
    int tid = threadIdx.x;
    int nbase = gblk * NPB;

    for (int i = tid * 4; i < 4096; i += 1024) {
        *(float4*)&sW[i]        = *(const float4*)&W0[i];
        *(float4*)&sW[4096 + i] = *(const float4*)&W1[i];
        *(float4*)&sW[8192 + i] = *(const float4*)&W2[i];
    }

    if (mode == 0) {
        if (tid < NPB * 3) {
            int nd = tid / 3, c = tid % 3;
            int node = nbase + nd;
            sX[tid] = (node < NN) ? __ldg(&in[node * 3 + c]) : 0.f;
        }
        __syncthreads();
        for (int i = tid; i < NPB * 64; i += 256) {
            int nd = i >> 6, k = i & 63;
            float v = fmaf(sX[nd * 3 + 0], __ldg(&Wn[k]),
                      fmaf(sX[nd * 3 + 1], __ldg(&Wn[64 + k]),
                      fmaf(sX[nd * 3 + 2], __ldg(&Wn[128 + k]), __ldg(&bn[k]))));
            sIn[nd * INPAD + k] = fmaxf(v, 0.f);
        }
    } else {
        for (int i = tid * 4; i < NPB * 64; i += 1024) {
            int nd = i >> 6, k = i & 63;
            int node = nbase + nd;
            float4 v = make_float4(0.f, 0.f, 0.f, 0.f);
            if (node < NN) v = *(const float4*)&in[node * 64 + k];
            v.x = fmaxf(v.x, 0.f); v.y = fmaxf(v.y, 0.f);
            v.z = fmaxf(v.z, 0.f); v.w = fmaxf(v.w, 0.f);
            *(float4*)&sIn[nd * INPAD + k] = v;
        }
    }
    __syncthreads();

    int tx = tid & 15, ty = tid >> 4;
    int c0 = tx * 4, n0 = ty * 4;
    float acc[3][4][4] = {};

    #pragma unroll 2
    for (int k = 0; k < 64; k++) {
        float4 w0 = *(float4*)&sW[k * 64 + c0];
        float4 w1 = *(float4*)&sW[4096 + k * 64 + c0];
        float4 w2 = *(float4*)&sW[8192 + k * 64 + c0];
        float a[4];
        #pragma unroll
        for (int j = 0; j < 4; j++) a[j] = sIn[(n0 + j) * INPAD + k];
        #pragma unroll
        for (int j = 0; j < 4; j++) {
            acc[0][j][0] = fmaf(a[j], w0.x, acc[0][j][0]);
            acc[0][j][1] = fmaf(a[j], w0.y, acc[0][j][1]);
            acc[0][j][2] = fmaf(a[j], w0.z, acc[0][j][2]);
            acc[0][j][3] = fmaf(a[j], w0.w, acc[0][j][3]);
            acc[1][j][0] = fmaf(a[j], w1.x, acc[1][j][0]);
            acc[1][j][1] = fmaf(a[j], w1.y, acc[1][j][1]);
            acc[1][j][2] = fmaf(a[j], w1.z, acc[1][j][2]);
            acc[1][j][3] = fmaf(a[j], w1.w, acc[1][j][3]);
            acc[2][j][0] = fmaf(a[j], w2.x, acc[2][j][0]);
            acc[2][j][1] = fmaf(a[j], w2.y, acc[2][j][1]);
            acc[2][j][2] = fmaf(a[j], w2.z, acc[2][j][2]);
            acc[2][j][3] = fmaf(a[j], w2.w, acc[2][j][3]);
        }
    }

    float4 bv = *(const float4*)&bias2[c0];
    #pragma unroll
    for (int j = 0; j < 4; j++) {
        int node = nbase + n0 + j;
        if (node >= NN) break;
        *(float4*)&o0[node * 64 + c0] =
            make_float4(acc[0][j][0], acc[0][j][1], acc[0][j][2], acc[0][j][3]);
        *(float4*)&o1[node * 64 + c0] =
            make_float4(acc[1][j][0], acc[1][j][1], acc[1][j][2], acc[1][j][3]);
        *(float4*)&o2[node * 64 + c0] =
            make_float4(acc[2][j][0] + bv.x, acc[2][j][1] + bv.y,
                        acc[2][j][2] + bv.z, acc[2][j][3] + bv.w);
    }
}

// conv1 front: blocks [0, GEMM_GRID) do gemm (mode 0), trailing blocks do CSR fill.
__global__ __launch_bounds__(256)
void k_conv1_front(const float* __restrict__ x,
                   const float* __restrict__ W0,
                   const float* __restrict__ W1,
                   const float* __restrict__ W2,
                   const float* __restrict__ bias2,
                   const float* __restrict__ Wn,
                   const float* __restrict__ bn,
                   float* __restrict__ o0,
                   float* __restrict__ o1,
                   float* __restrict__ o2,
                   const int* __restrict__ ei,
                   const float* __restrict__ ea,
                   const int* __restrict__ et) {
    if (blockIdx.x < GEMM_GRID) {
        gemm_body(blockIdx.x, x, W0, W1, W2, bias2, Wn, bn, o0, o1, o2, 0);
    } else {
        int e = (blockIdx.x - GEMM_GRID) * blockDim.x + threadIdx.x;
        if (e >= NE) return;
        int dst = ei[NE + e];
        int pos = atomicAdd(&g_cur[dst], 1);
        unsigned pk = (unsigned)ei[e] | ((unsigned)et[e] << 31);
        float2 a = ((const float2*)ea)[e];
        g_csr_pk[pos] = pk;
        g_csr_ed[pos] = make_uint4(pk, __float_as_uint(a.x), __float_as_uint(a.y), 0u);
    }
}

// conv2 node-side GEMM (mode 1)
__global__ __launch_bounds__(256)
void k_gemm3(const float* __restrict__ in,
             const float* __restrict__ W0,
             const float* __restrict__ W1,
             const float* __restrict__ W2,
             const float* __restrict__ bias2,
             float* __restrict__ o0,
             float* __restrict__ o1,
             float* __restrict__ o2) {
    gemm_body(blockIdx.x, in, W0, W1, W2, bias2, nullptr, nullptr, o0, o1, o2, 1);
}

// ---------------------------------------------------------------------------
// conv1 gather: one warp per dst node; 4-edge unroll (MLP=4).
//   msum  = sum_e m_{typ}[src]          (lane owns cols 2l, 2l+1)
//   aggev = sum_e relu(ea@We+be)        (lane owns dim l of 32)
//   hpre  = r1 + msum + aggev @ W1_edge
// ---------------------------------------------------------------------------
__global__ void k_gather1(const float* __restrict__ We,
                          const float* __restrict__ be,
                          const float* __restrict__ W1e) {
    __shared__ float  sWe0[32], sWe1[32], sbe[32];
    __shared__ float2 sW1e[32 * 32];
    int tid = threadIdx.x;
    if (tid < 32) { sWe0[tid] = We[tid]; sWe1[tid] = We[32 + tid]; sbe[tid] = be[tid]; }
    for (int i = tid; i < 1024; i += blockDim.x)
        sW1e[i] = ((const float2*)W1e)[i];
    __syncthreads();

    int lane = tid & 31;
    int node = (blockIdx.x * blockDim.x + tid) >> 5;
    if (node >= NN) return;
    int s0 = g_off[node], s1 = g_off[node + 1];

    float  ev = 0.f;
    float2 ms = make_float2(0.f, 0.f);
    int e = s0;
    for (; e + 4 <= s1; e += 4) {
        uint4 d0 = __ldg(&g_csr_ed[e]);
        uint4 d1 = __ldg(&g_csr_ed[e + 1]);
        uint4 d2 = __ldg(&g_csr_ed[e + 2]);
        uint4 d3 = __ldg(&g_csr_ed[e + 3]);
        const float2* t0 = (d0.x >> 31) ? (const float2*)g_m1 : (const float2*)g_m0;
        const float2* t1 = (d1.x >> 31) ? (const float2*)g_m1 : (const float2*)g_m0;
        const float2* t2 = (d2.x >> 31) ? (const float2*)g_m1 : (const float2*)g_m0;
        const float2* t3 = (d3.x >> 31) ? (const float2*)g_m1 : (const float2*)g_m0;
        float2 v0 = __ldg(&t0[(d0.x & 0x7FFFFFFFu) * 32 + lane]);
        float2 v1 = __ldg(&t1[(d1.x & 0x7FFFFFFFu) * 32 + lane]);
        float2 v2 = __ldg(&t2[(d2.x & 0x7FFFFFFFu) * 32 + lane]);
        float2 v3 = __ldg(&t3[(d3.x & 0x7FFFFFFFu) * 32 + lane]);
        ev += fmaxf(fmaf(__uint_as_float(d0.y), sWe0[lane],
                    fmaf(__uint_as_float(d0.z), sWe1[lane], sbe[lane])), 0.f);
        ev += fmaxf(fmaf(__uint_as_float(d1.y), sWe0[lane],
                    fmaf(__uint_as_float(d1.z), sWe1[lane], sbe[lane])), 0.f);
        ev += fmaxf(fmaf(__uint_as_float(d2.y), sWe0[lane],
                    fmaf(__uint_as_float(d2.z), sWe1[lane], sbe[lane])), 0.f);
        ev += fmaxf(fmaf(__uint_as_float(d3.y), sWe0[lane],
                    fmaf(__uint_as_float(d3.z), sWe1[lane], sbe[lane])), 0.f);
        ms.x += (v0.x + v1.x) + (v2.x + v3.x);
        ms.y += (v0.y + v1.y) + (v2.y + v3.y);
    }
    for (; e < s1; e++) {
        uint4 d = __ldg(&g_csr_ed[e]);
        ev += fmaxf(fmaf(__uint_as_float(d.y), sWe0[lane],
                    fmaf(__uint_as_float(d.z), sWe1[lane], sbe[lane])), 0.f);
        const float2* m = (d.x >> 31) ? (const float2*)g_m1 : (const float2*)g_m0;
        float2 v = __ldg(&m[(d.x & 0x7FFFFFFFu) * 32 + lane]);
        ms.x += v.x; ms.y += v.y;
    }

    float2 acc = make_float2(0.f, 0.f);
    #pragma unroll
    for (int k = 0; k < 32; k++) {
        float ek = __shfl_sync(FULL, ev, k);
        float2 w = sW1e[k * 32 + lane];
        acc.x = fmaf(ek, w.x, acc.x);
        acc.y = fmaf(ek, w.y, acc.y);
    }
    float2 r = *(const float2*)&g_r1[node * 64 + 2 * lane];
    *(float2*)&g_hpre[node * 64 + 2 * lane] =
        make_float2(r.x + ms.x + acc.x, r.y + ms.y + acc.y);
}

// ---------------------------------------------------------------------------
// conv2 gather + readout: one warp per dst node; 4-edge unroll.
//   mx = max_e p_{typ}[src] (0 for empty); h2 = relu(mx + r2)
//   out = tanh(h2 @ Wc + bc) * 5
// ---------------------------------------------------------------------------
__global__ void k_gather2(const float* __restrict__ Wc,
                          const float* __restrict__ bc,
                          float* __restrict__ out) {
    int tid  = threadIdx.x;
    int lane = tid & 31;
    int node = (blockIdx.x * blockDim.x + tid) >> 5;
    if (node >= NN) return;
    int s0 = g_off[node], s1 = g_off[node + 1];

    float2 mx = make_float2(-CUDART_INF_F, -CUDART_INF_F);
    int e = s0;
    for (; e + 4 <= s1; e += 4) {
        unsigned k0 = __ldg(&g_csr_pk[e]);
        unsigned k1 = __ldg(&g_csr_pk[e + 1]);
        unsigned k2 = __ldg(&g_csr_pk[e + 2]);
        unsigned k3 = __ldg(&g_csr_pk[e + 3]);
        const float2* t0 = (k0 >> 31) ? (const float2*)g_p1 : (const float2*)g_p0;
        const float2* t1 = (k1 >> 31) ? (const float2*)g_p1 : (const float2*)g_p0;
        const float2* t2 = (k2 >> 31) ? (const float2*)g_p1 : (const float2*)g_p0;
        const float2* t3 = (k3 >> 31) ? (const float2*)g_p1 : (const float2*)g_p0;
        float2 v0 = __ldg(&t0[(k0 & 0x7FFFFFFFu) * 32 + lane]);
        float2 v1 = __ldg(&t1[(k1 & 0x7FFFFFFFu) * 32 + lane]);
        float2 v2 = __ldg(&t2[(k2 & 0x7FFFFFFFu) * 32 + lane]);
        float2 v3 = __ldg(&t3[(k3 & 0x7FFFFFFFu) * 32 + lane]);
        mx.x = fmaxf(mx.x, fmaxf(fmaxf(v0.x, v1.x), fmaxf(v2.x, v3.x)));
        mx.y = fmaxf(mx.y, fmaxf(fmaxf(v0.y, v1.y), fmaxf(v2.y, v3.y)));
    }
    for (; e < s1; e++) {
        unsigned pk = __ldg(&g_csr_pk[e]);
        const float2* p = (pk >> 31) ? (const float2*)g_p1 : (const float2*)g_p0;
        float2 v = __ldg(&p[(pk & 0x7FFFFFFFu) * 32 + lane]);
        mx.x = fmaxf(mx.x, v.x);
        mx.y = fmaxf(mx.y, v.y);
    }
    if (s1 == s0) mx = make_float2(0.f, 0.f);

    float2 r = *(const float2*)&g_r2[node * 64 + 2 * lane];
    float h0 = fmaxf(mx.x + r.x, 0.f);
    float h1 = fmaxf(mx.y + r.y, 0.f);
    float p = fmaf(h0, __ldg(&Wc[2 * lane]), h1 * __ldg(&Wc[2 * lane + 1]));
    #pragma unroll
    for (int o = 16; o > 0; o >>= 1) p += __shfl_xor_sync(FULL, p, o);
    if (lane == 0) out[node] = tanhf(p + __ldg(bc)) * 5.0f;
}

// ---------------------------------------------------------------------------
// launch
// ---------------------------------------------------------------------------
extern "C" void kernel_launch(void* const* d_in, const int* in_sizes, int n_in,
                              void* d_out, int out_size) {
    const float* x      = (const float*)d_in[0];
    const int*   ei     = (const int*)  d_in[1];
    const float* ea     = (const float*)d_in[2];
    const int*   et     = (const int*)  d_in[3];
    const float* Wn     = (const float*)d_in[4];
    const float* bn     = (const float*)d_in[5];
    const float* We     = (const float*)d_in[6];
    const float* be     = (const float*)d_in[7];
    const float* W1_rel = (const float*)d_in[8];
    const float* W1_edge= (const float*)d_in[9];
    const float* W1_root= (const float*)d_in[10];
    const float* b1     = (const float*)d_in[11];
    const float* W2_rel = (const float*)d_in[12];
    const float* W2_root= (const float*)d_in[13];
    const float* b2     = (const float*)d_in[14];
    const float* Wc     = (const float*)d_in[15];
    const float* bc     = (const float*)d_in[16];
    float* out          = (float*)d_out;

    float *pm0, *pm1, *pr1, *phpre, *pp0, *pp1, *pr2;
    int* pdeg;
    cudaGetSymbolAddress((void**)&pm0,   g_m0);
    cudaGetSymbolAddress((void**)&pm1,   g_m1);
    cudaGetSymbolAddress((void**)&pr1,   g_r1);
    cudaGetSymbolAddress((void**)&phpre, g_hpre);
    cudaGetSymbolAddress((void**)&pp0,   g_p0);
    cudaGetSymbolAddress((void**)&pp1,   g_p1);
    cudaGetSymbolAddress((void**)&pr2,   g_r2);
    cudaGetSymbolAddress((void**)&pdeg,  g_deg);

    static const int SMEM = (3 * 4096 + NPB * INPAD) * sizeof(float);
    cudaFuncSetAttribute(k_conv1_front, cudaFuncAttributeMaxDynamicSharedMemorySize, SMEM);
    cudaFuncSetAttribute(k_gemm3,       cudaFuncAttributeMaxDynamicSharedMemorySize, SMEM);

    const int edgeBlocks     = (NE + 255) / 256;
    const int nodeWarpBlocks = (NN * 32 + 255) / 256;

    // CSR degree + offsets
    cudaMemsetAsync(pdeg, 0, NN * sizeof(int));
    k_hist<<<edgeBlocks, 256>>>(ei);
    k_scan<<<1, 1024>>>();

    // conv1 node-side GEMMs (embed fused) + CSR fill packed into one launch:
    // blocks [0,782) gemm, [782, 782+3125) fill edges.
    k_conv1_front<<<GEMM_GRID + edgeBlocks, 256, SMEM>>>(
        x, W1_rel, W1_rel + 4096, W1_root, b1, Wn, bn,
        pm0, pm1, pr1, ei, ea, et);

    // conv1 gather (sum) + edge-feature fold
    k_gather1<<<nodeWarpBlocks, 256>>>(We, be, W1_edge);

    // conv2 node-side: h = relu(hpre) fused; p0, p1, r2
    k_gemm3<<<GEMM_GRID, 256, SMEM>>>(phpre, W2_rel, W2_rel + 4096, W2_root, b2,
                                      pp0, pp1, pr2);

    // conv2 gather (max) + readout fused
    k_gather2<<<nodeWarpBlocks, 256>>>(Wc, bc, out);
}

// round 6
// speedup vs baseline: 1.0555x; 1.0075x over previous
#include <cuda_runtime.h>
#include <cuda_bf16.h>
#include <math_constants.h>

#define NN 50000
#define NE 800000
#define HID 64
#define FULL 0xffffffffu

// ---------------------------------------------------------------------------
// Scratch (device globals; allocation-free per harness rules)
// ---------------------------------------------------------------------------
// Interleaved relation tables: row = 128 floats = [m_rel0 (64) | m_rel1 (64)]
__device__ __align__(16) float    g_mm  [NN * 128];   // conv1: n @ W1_rel[r]
__device__ __align__(16) float    g_pp  [NN * 128];   // conv2: h @ W2_rel[r]
__device__ __align__(16) float    g_r1  [NN * HID];   // n @ W1_root + b1
__device__ __align__(16) float    g_hpre[NN * HID];   // pre-relu h (conv1 out)
__device__ __align__(16) float    g_r2  [NN * HID];   // h @ W2_root + b2
// CSR by dst
__device__ int      g_deg[NN];
__device__ int      g_off[NN + 1];
__device__ int      g_cur[NN];
__device__ unsigned g_csr_pk[NE];            // premultiplied f2 offset: src*64 + typ*32
__device__ __align__(16) uint4 g_csr_ed[NE]; // {off, ea.x, ea.y, 0}

// ---------------------------------------------------------------------------
// Vectorized single-block scan (1024 thr, 4 elems/thread/pass)
// ---------------------------------------------------------------------------
__global__ void k_scan() {
    __shared__ int warpsum[32];
    int tid  = threadIdx.x;
    int lane = tid & 31;
    int wid  = tid >> 5;
    int carry = 0;
    for (int base = 0; base < NN; base += 4096) {
        int i0 = base + tid * 4;
        int v[4];
        #pragma unroll
        for (int j = 0; j < 4; j++) v[j] = (i0 + j < NN) ? g_deg[i0 + j] : 0;
        int tsum = (v[0] + v[1]) + (v[2] + v[3]);
        int s = tsum;
        #pragma unroll
        for (int o = 1; o < 32; o <<= 1) {
            int t = __shfl_up_sync(FULL, s, o);
            if (lane >= o) s += t;
        }
        if (lane == 31) warpsum[wid] = s;
        __syncthreads();
        if (wid == 0) {
            int ws = warpsum[lane];
            #pragma unroll
            for (int o = 1; o < 32; o <<= 1) {
                int t = __shfl_up_sync(FULL, ws, o);
                if (lane >= o) ws += t;
            }
            warpsum[lane] = ws;
        }
        __syncthreads();
        int wpre = (wid > 0) ? warpsum[wid - 1] : 0;
        int run  = carry + wpre + s - tsum;
        #pragma unroll
        for (int j = 0; j < 4; j++) {
            if (i0 + j < NN) { g_off[i0 + j] = run; g_cur[i0 + j] = run; run += v[j]; }
        }
        int total = warpsum[31];
        __syncthreads();
        carry += total;
    }
    if (tid == 0) g_off[NN] = NE;
}

// ---------------------------------------------------------------------------
// CSR fill (after scan): premultiplied offsets into interleaved tables
// ---------------------------------------------------------------------------
__global__ void k_fill(const int* __restrict__ ei,
                       const float* __restrict__ ea,
                       const int* __restrict__ et) {
    int e = blockIdx.x * blockDim.x + threadIdx.x;
    if (e >= NE) return;
    int dst = ei[NE + e];
    int pos = atomicAdd(&g_cur[dst], 1);
    unsigned off = (unsigned)ei[e] * 64u + (unsigned)et[e] * 32u;  // float2 units
    float2 a = ((const float2*)ea)[e];
    g_csr_pk[pos] = off;
    g_csr_ed[pos] = make_uint4(off, __float_as_uint(a.x), __float_as_uint(a.y), 0u);
}

// ---------------------------------------------------------------------------
// GEMM body (round-2 datapath):
//   o0/o1 -> interleaved table (row stride 128), o2 -> dense (stride 64, +bias)
// mode 0: f(in) = relu(x@Wn+bn) fused;  mode 1: f(in) = relu(in)
// ---------------------------------------------------------------------------
#define NPB 64
#define INPAD 68
#define GEMM_GRID ((NN + NPB - 1) / NPB)     // 782
extern __shared__ float s_dyn[];

__device__ __forceinline__ void gemm_body(
        int gblk,
        const float* __restrict__ in,
        const float* __restrict__ W0,
        const float* __restrict__ W1,
        const float* __restrict__ W2,
        const float* __restrict__ bias2,
        const float* __restrict__ Wn,
        const float* __restrict__ bn,
        float* __restrict__ oAB,     // interleaved table base (stride 128)
        float* __restrict__ o2,      // dense (stride 64)
        int mode) {
    float* sW  = s_dyn;                 // 3 * 64 * 64
    float* sIn = s_dyn + 3 * 4096;      // 64 * INPAD
    __shared__ float sX[NPB * 3];
    int tid = threadIdx.x;
    int nbase = gblk * NPB;

    for (int i = tid * 4; i < 4096; i += 1024) {
        *(float4*)&sW[i]        = *(const float4*)&W0[i];
        *(float4*)&sW[4096 + i] = *(const float4*)&W1[i];
        *(float4*)&sW[8192 + i] = *(const float4*)&W2[i];
    }

    if (mode == 0) {
        if (tid < NPB * 3) {
            int nd = tid / 3, c = tid % 3;
            int node = nbase + nd;
            sX[tid] = (node < NN) ? __ldg(&in[node * 3 + c]) : 0.f;
        }
        __syncthreads();
        for (int i = tid; i < NPB * 64; i += 256) {
            int nd = i >> 6, k = i & 63;
            float v = fmaf(sX[nd * 3 + 0], __ldg(&Wn[k]),
                      fmaf(sX[nd * 3 + 1], __ldg(&Wn[64 + k]),
                      fmaf(sX[nd * 3 + 2], __ldg(&Wn[128 + k]), __ldg(&bn[k]))));
            sIn[nd * INPAD + k] = fmaxf(v, 0.f);
        }
    } else {
        for (int i = tid * 4; i < NPB * 64; i += 1024) {
            int nd = i >> 6, k = i & 63;
            int node = nbase + nd;
            float4 v = make_float4(0.f, 0.f, 0.f, 0.f);
            if (node < NN) v = *(const float4*)&in[node * 64 + k];
            v.x = fmaxf(v.x, 0.f); v.y = fmaxf(v.y, 0.f);
            v.z = fmaxf(v.z, 0.f); v.w = fmaxf(v.w, 0.f);
            *(float4*)&sIn[nd * INPAD + k] = v;
        }
    }
    __syncthreads();

    int tx = tid & 15, ty = tid >> 4;
    int c0 = tx * 4, n0 = ty * 4;
    float acc[3][4][4] = {};

    #pragma unroll 2
    for (int k = 0; k < 64; k++) {
        float4 w0 = *(float4*)&sW[k * 64 + c0];
        float4 w1 = *(float4*)&sW[4096 + k * 64 + c0];
        float4 w2 = *(float4*)&sW[8192 + k * 64 + c0];
        float a[4];
        #pragma unroll
        for (int j = 0; j < 4; j++) a[j] = sIn[(n0 + j) * INPAD + k];
        #pragma unroll
        for (int j = 0; j < 4; j++) {
            acc[0][j][0] = fmaf(a[j], w0.x, acc[0][j][0]);
            acc[0][j][1] = fmaf(a[j], w0.y, acc[0][j][1]);
            acc[0][j][2] = fmaf(a[j], w0.z, acc[0][j][2]);
            acc[0][j][3] = fmaf(a[j], w0.w, acc[0][j][3]);
            acc[1][j][0] = fmaf(a[j], w1.x, acc[1][j][0]);
            acc[1][j][1] = fmaf(a[j], w1.y, acc[1][j][1]);
            acc[1][j][2] = fmaf(a[j], w1.z, acc[1][j][2]);
            acc[1][j][3] = fmaf(a[j], w1.w, acc[1][j][3]);
            acc[2][j][0] = fmaf(a[j], w2.x, acc[2][j][0]);
            acc[2][j][1] = fmaf(a[j], w2.y, acc[2][j][1]);
            acc[2][j][2] = fmaf(a[j], w2.z, acc[2][j][2]);
            acc[2][j][3] = fmaf(a[j], w2.w, acc[2][j][3]);
        }
    }

    float4 bv = *(const float4*)&bias2[c0];
    #pragma unroll
    for (int j = 0; j < 4; j++) {
        int node = nbase + n0 + j;
        if (node >= NN) break;
        *(float4*)&oAB[node * 128 + c0] =
            make_float4(acc[0][j][0], acc[0][j][1], acc[0][j][2], acc[0][j][3]);
        *(float4*)&oAB[node * 128 + 64 + c0] =
            make_float4(acc[1][j][0], acc[1][j][1], acc[1][j][2], acc[1][j][3]);
        *(float4*)&o2[node * 64 + c0] =
            make_float4(acc[2][j][0] + bv.x, acc[2][j][1] + bv.y,
                        acc[2][j][2] + bv.z, acc[2][j][3] + bv.w);
    }
}

// conv1 front: blocks [0, GEMM_GRID) gemm (mode 0); trailing blocks: degree hist.
__global__ __launch_bounds__(256)
void k_conv1_front(const float* __restrict__ x,
                   const float* __restrict__ W0,
                   const float* __restrict__ W1,
                   const float* __restrict__ W2,
                   const float* __restrict__ bias2,
                   const float* __restrict__ Wn,
                   const float* __restrict__ bn,
                   float* __restrict__ oAB,
                   float* __restrict__ o2,
                   const int* __restrict__ ei) {
    if (blockIdx.x < GEMM_GRID) {
        gemm_body(blockIdx.x, x, W0, W1, W2, bias2, Wn, bn, oAB, o2, 0);
    } else {
        int e = (blockIdx.x - GEMM_GRID) * blockDim.x + threadIdx.x;
        if (e < NE) atomicAdd(&g_deg[ei[NE + e]], 1);
    }
}

// conv2 node-side GEMM (mode 1)
__global__ __launch_bounds__(256)
void k_gemm3(const float* __restrict__ in,
             const float* __restrict__ W0,
             const float* __restrict__ W1,
             const float* __restrict__ W2,
             const float* __restrict__ bias2,
             float* __restrict__ oAB,
             float* __restrict__ o2) {
    gemm_body(blockIdx.x, in, W0, W1, W2, bias2, nullptr, nullptr, oAB, o2, 1);
}

// ---------------------------------------------------------------------------
// conv1 gather: one warp per dst node; 4-edge unroll; premultiplied offsets.
// ---------------------------------------------------------------------------
__global__ __launch_bounds__(256, 6)
void k_gather1(const float* __restrict__ We,
               const float* __restrict__ be,
               const float* __restrict__ W1e) {
    __shared__ float  sWe0[32], sWe1[32], sbe[32];
    __shared__ float2 sW1e[32 * 32];
    int tid = threadIdx.x;
    if (tid < 32) { sWe0[tid] = We[tid]; sWe1[tid] = We[32 + tid]; sbe[tid] = be[tid]; }
    for (int i = tid; i < 1024; i += blockDim.x)
        sW1e[i] = ((const float2*)W1e)[i];
    __syncthreads();

    int lane = tid & 31;
    int node = (blockIdx.x * blockDim.x + tid) >> 5;
    if (node >= NN) return;
    int s0 = g_off[node], s1 = g_off[node + 1];
    const float2* mm2 = (const float2*)g_mm;

    float we0 = sWe0[lane], we1 = sWe1[lane], beL = sbe[lane];
    float  ev = 0.f;
    float2 ms = make_float2(0.f, 0.f);
    int e = s0;
    for (; e + 4 <= s1; e += 4) {
        uint4 d0 = __ldg(&g_csr_ed[e]);
        uint4 d1 = __ldg(&g_csr_ed[e + 1]);
        uint4 d2 = __ldg(&g_csr_ed[e + 2]);
        uint4 d3 = __ldg(&g_csr_ed[e + 3]);
        float2 v0 = __ldg(&mm2[d0.x + lane]);
        float2 v1 = __ldg(&mm2[d1.x + lane]);
        float2 v2 = __ldg(&mm2[d2.x + lane]);
        float2 v3 = __ldg(&mm2[d3.x + lane]);
        ev += fmaxf(fmaf(__uint_as_float(d0.y), we0,
                    fmaf(__uint_as_float(d0.z), we1, beL)), 0.f);
        ev += fmaxf(fmaf(__uint_as_float(d1.y), we0,
                    fmaf(__uint_as_float(d1.z), we1, beL)), 0.f);
        ev += fmaxf(fmaf(__uint_as_float(d2.y), we0,
                    fmaf(__uint_as_float(d2.z), we1, beL)), 0.f);
        ev += fmaxf(fmaf(__uint_as_float(d3.y), we0,
                    fmaf(__uint_as_float(d3.z), we1, beL)), 0.f);
        ms.x += (v0.x + v1.x) + (v2.x + v3.x);
        ms.y += (v0.y + v1.y) + (v2.y + v3.y);
    }
    for (; e < s1; e++) {
        uint4 d = __ldg(&g_csr_ed[e]);
        ev += fmaxf(fmaf(__uint_as_float(d.y), we0,
                    fmaf(__uint_as_float(d.z), we1, beL)), 0.f);
        float2 v = __ldg(&mm2[d.x + lane]);
        ms.x += v.x; ms.y += v.y;
    }

    float2 acc = make_float2(0.f, 0.f);
    #pragma unroll
    for (int k = 0; k < 32; k++) {
        float ek = __shfl_sync(FULL, ev, k);
        float2 w = sW1e[k * 32 + lane];
        acc.x = fmaf(ek, w.x, acc.x);
        acc.y = fmaf(ek, w.y, acc.y);
    }
    float2 r = *(const float2*)&g_r1[node * 64 + 2 * lane];
    *(float2*)&g_hpre[node * 64 + 2 * lane] =
        make_float2(r.x + ms.x + acc.x, r.y + ms.y + acc.y);
}

// ---------------------------------------------------------------------------
// conv2 gather + readout: one warp per dst node; 4-edge unroll.
// ---------------------------------------------------------------------------
__global__ __launch_bounds__(256, 6)
void k_gather2(const float* __restrict__ Wc,
               const float* __restrict__ bc,
               float* __restrict__ out) {
    int tid  = threadIdx.x;
    int lane = tid & 31;
    int node = (blockIdx.x * blockDim.x + tid) >> 5;
    if (node >= NN) return;
    int s0 = g_off[node], s1 = g_off[node + 1];
    const float2* pp2 = (const float2*)g_pp;

    float2 mx = make_float2(-CUDART_INF_F, -CUDART_INF_F);
    int e = s0;
    for (; e + 4 <= s1; e += 4) {
        unsigned k0 = __ldg(&g_csr_pk[e]);
        unsigned k1 = __ldg(&g_csr_pk[e + 1]);
        unsigned k2 = __ldg(&g_csr_pk[e + 2]);
        unsigned k3 = __ldg(&g_csr_pk[e + 3]);
        float2 v0 = __ldg(&pp2[k0 + lane]);
        float2 v1 = __ldg(&pp2[k1 + lane]);
        float2 v2 = __ldg(&pp2[k2 + lane]);
        float2 v3 = __ldg(&pp2[k3 + lane]);
        mx.x = fmaxf(mx.x, fmaxf(fmaxf(v0.x, v1.x), fmaxf(v2.x, v3.x)));
        mx.y = fmaxf(mx.y, fmaxf(fmaxf(v0.y, v1.y), fmaxf(v2.y, v3.y)));
    }
    for (; e < s1; e++) {
        unsigned pk = __ldg(&g_csr_pk[e]);
        float2 v = __ldg(&pp2[pk + lane]);
        mx.x = fmaxf(mx.x, v.x);
        mx.y = fmaxf(mx.y, v.y);
    }
    if (s1 == s0) mx = make_float2(0.f, 0.f);

    float2 r = *(const float2*)&g_r2[node * 64 + 2 * lane];
    float h0 = fmaxf(mx.x + r.x, 0.f);
    float h1 = fmaxf(mx.y + r.y, 0.f);
    float p = fmaf(h0, __ldg(&Wc[2 * lane]), h1 * __ldg(&Wc[2 * lane + 1]));
    #pragma unroll
    for (int o = 16; o > 0; o >>= 1) p += __shfl_xor_sync(FULL, p, o);
    if (lane == 0) out[node] = tanhf(p + __ldg(bc)) * 5.0f;
}

// ---------------------------------------------------------------------------
// launch
// ---------------------------------------------------------------------------
extern "C" void kernel_launch(void* const* d_in, const int* in_sizes, int n_in,
                              void* d_out, int out_size) {
    const float* x      = (const float*)d_in[0];
    const int*   ei     = (const int*)  d_in[1];
    const float* ea     = (const float*)d_in[2];
    const int*   et     = (const int*)  d_in[3];
    const float* Wn     = (const float*)d_in[4];
    const float* bn     = (const float*)d_in[5];
    const float* We     = (const float*)d_in[6];
    const float* be     = (const float*)d_in[7];
    const float* W1_rel = (const float*)d_in[8];
    const float* W1_edge= (const float*)d_in[9];
    const float* W1_root= (const float*)d_in[10];
    const float* b1     = (const float*)d_in[11];
    const float* W2_rel = (const float*)d_in[12];
    const float* W2_root= (const float*)d_in[13];
    const float* b2     = (const float*)d_in[14];
    const float* Wc     = (const float*)d_in[15];
    const float* bc     = (const float*)d_in[16];
    float* out          = (float*)d_out;

    float *pmm, *ppp, *pr1, *phpre, *pr2;
    int* pdeg;
    cudaGetSymbolAddress((void**)&pmm,   g_mm);
    cudaGetSymbolAddress((void**)&ppp,   g_pp);
    cudaGetSymbolAddress((void**)&pr1,   g_r1);
    cudaGetSymbolAddress((void**)&phpre, g_hpre);
    cudaGetSymbolAddress((void**)&pr2,   g_r2);
    cudaGetSymbolAddress((void**)&pdeg,  g_deg);

    static const int SMEM = (3 * 4096 + NPB * INPAD) * sizeof(float);
    cudaFuncSetAttribute(k_conv1_front, cudaFuncAttributeMaxDynamicSharedMemorySize, SMEM);
    cudaFuncSetAttribute(k_gemm3,       cudaFuncAttributeMaxDynamicSharedMemorySize, SMEM);

    const int edgeBlocks     = (NE + 255) / 256;
    const int nodeWarpBlocks = (NN * 32 + 255) / 256;

    cudaMemsetAsync(pdeg, 0, NN * sizeof(int));

    // conv1 node-side GEMMs (embed fused) + degree histogram in tail blocks
    k_conv1_front<<<GEMM_GRID + edgeBlocks, 256, SMEM>>>(
        x, W1_rel, W1_rel + 4096, W1_root, b1, Wn, bn, pmm, pr1, ei);

    // CSR offsets + fill
    k_scan<<<1, 1024>>>();
    k_fill<<<edgeBlocks, 256>>>(ei, ea, et);

    // conv1 gather (sum) + edge-feature fold
    k_gather1<<<nodeWarpBlocks, 256>>>(We, be, W1_edge);

    // conv2 node-side: h = relu(hpre) fused; pp table + r2
    k_gemm3<<<GEMM_GRID, 256, SMEM>>>(phpre, W2_rel, W2_rel + 4096, W2_root, b2,
                                      ppp, pr2);

    // conv2 gather (max) + readout fused
    k_gather2<<<nodeWarpBlocks, 256>>>(Wc, bc, out);
}

// round 7
// speedup vs baseline: 1.1092x; 1.0509x over previous
#include <cuda_runtime.h>
#include <cuda_bf16.h>
#include <math_constants.h>

#define NN 50000
#define NE 800000
#define HID 64
#define FULL 0xffffffffu

// ---------------------------------------------------------------------------
// Scratch (device globals; allocation-free per harness rules)
// ---------------------------------------------------------------------------
// Interleaved relation tables: row = 128 floats = [m_rel0 (64) | m_rel1 (64)]
__device__ __align__(16) float    g_mm  [NN * 128];   // conv1: n @ W1_rel[r]
__device__ __align__(16) float    g_pp  [NN * 128];   // conv2: h @ W2_rel[r]
__device__ __align__(16) float    g_r1  [NN * HID];   // n @ W1_root + b1
__device__ __align__(16) float    g_hpre[NN * HID];   // pre-relu h (conv1 out)
__device__ __align__(16) float    g_r2  [NN * HID];   // h @ W2_root + b2
// CSR by dst
__device__ int      g_deg[NN];
__device__ int      g_off[NN + 1];
__device__ int      g_cur[NN];
__device__ __align__(16) uint4 g_csr_ed[NE]; // {off(src*64+typ*32), ea.x, ea.y, 0}

// ---------------------------------------------------------------------------
// Vectorized single-block scan (1024 thr, 4 elems/thread/pass)
// ---------------------------------------------------------------------------
__global__ void k_scan() {
    __shared__ int warpsum[32];
    int tid  = threadIdx.x;
    int lane = tid & 31;
    int wid  = tid >> 5;
    int carry = 0;
    for (int base = 0; base < NN; base += 4096) {
        int i0 = base + tid * 4;
        int v[4];
        #pragma unroll
        for (int j = 0; j < 4; j++) v[j] = (i0 + j < NN) ? g_deg[i0 + j] : 0;
        int tsum = (v[0] + v[1]) + (v[2] + v[3]);
        int s = tsum;
        #pragma unroll
        for (int o = 1; o < 32; o <<= 1) {
            int t = __shfl_up_sync(FULL, s, o);
            if (lane >= o) s += t;
        }
        if (lane == 31) warpsum[wid] = s;
        __syncthreads();
        if (wid == 0) {
            int ws = warpsum[lane];
            #pragma unroll
            for (int o = 1; o < 32; o <<= 1) {
                int t = __shfl_up_sync(FULL, ws, o);
                if (lane >= o) ws += t;
            }
            warpsum[lane] = ws;
        }
        __syncthreads();
        int wpre = (wid > 0) ? warpsum[wid - 1] : 0;
        int run  = carry + wpre + s - tsum;
        #pragma unroll
        for (int j = 0; j < 4; j++) {
            if (i0 + j < NN) { g_off[i0 + j] = run; g_cur[i0 + j] = run; run += v[j]; }
        }
        int total = warpsum[31];
        __syncthreads();
        carry += total;
    }
    if (tid == 0) g_off[NN] = NE;
}

// ---------------------------------------------------------------------------
// CSR fill (after scan): premultiplied offsets into interleaved tables
// ---------------------------------------------------------------------------
__global__ void k_fill(const int* __restrict__ ei,
                       const float* __restrict__ ea,
                       const int* __restrict__ et) {
    int e = blockIdx.x * blockDim.x + threadIdx.x;
    if (e >= NE) return;
    int dst = ei[NE + e];
    int pos = atomicAdd(&g_cur[dst], 1);
    unsigned off = (unsigned)ei[e] * 64u + (unsigned)et[e] * 32u;  // float2 units
    float2 a = ((const float2*)ea)[e];
    g_csr_ed[pos] = make_uint4(off, __float_as_uint(a.x), __float_as_uint(a.y), 0u);
}

// ---------------------------------------------------------------------------
// GEMM body (round-2 datapath):
//   o0/o1 -> interleaved table (row stride 128), o2 -> dense (stride 64, +bias)
// mode 0: f(in) = relu(x@Wn+bn) fused;  mode 1: f(in) = relu(in)
// ---------------------------------------------------------------------------
#define NPB 64
#define INPAD 68
#define GEMM_GRID ((NN + NPB - 1) / NPB)     // 782
extern __shared__ float s_dyn[];

__device__ __forceinline__ void gemm_body(
        int gblk,
        const float* __restrict__ in,
        const float* __restrict__ W0,
        const float* __restrict__ W1,
        const float* __restrict__ W2,
        const float* __restrict__ bias2,
        const float* __restrict__ Wn,
        const float* __restrict__ bn,
        float* __restrict__ oAB,     // interleaved table base (stride 128)
        float* __restrict__ o2,      // dense (stride 64)
        int mode) {
    float* sW  = s_dyn;                 // 3 * 64 * 64
    float* sIn = s_dyn + 3 * 4096;      // 64 * INPAD
    __shared__ float sX[NPB * 3];
    int tid = threadIdx.x;
    int nbase = gblk * NPB;

    for (int i = tid * 4; i < 4096; i += 1024) {
        *(float4*)&sW[i]        = *(const float4*)&W0[i];
        *(float4*)&sW[4096 + i] = *(const float4*)&W1[i];
        *(float4*)&sW[8192 + i] = *(const float4*)&W2[i];
    }

    if (mode == 0) {
        if (tid < NPB * 3) {
            int nd = tid / 3, c = tid % 3;
            int node = nbase + nd;
            sX[tid] = (node < NN) ? __ldg(&in[node * 3 + c]) : 0.f;
        }
        __syncthreads();
        for (int i = tid; i < NPB * 64; i += 256) {
            int nd = i >> 6, k = i & 63;
            float v = fmaf(sX[nd * 3 + 0], __ldg(&Wn[k]),
                      fmaf(sX[nd * 3 + 1], __ldg(&Wn[64 + k]),
                      fmaf(sX[nd * 3 + 2], __ldg(&Wn[128 + k]), __ldg(&bn[k]))));
            sIn[nd * INPAD + k] = fmaxf(v, 0.f);
        }
    } else {
        for (int i = tid * 4; i < NPB * 64; i += 1024) {
            int nd = i >> 6, k = i & 63;
            int node = nbase + nd;
            float4 v = make_float4(0.f, 0.f, 0.f, 0.f);
            if (node < NN) v = *(const float4*)&in[node * 64 + k];
            v.x = fmaxf(v.x, 0.f); v.y = fmaxf(v.y, 0.f);
            v.z = fmaxf(v.z, 0.f); v.w = fmaxf(v.w, 0.f);
            *(float4*)&sIn[nd * INPAD + k] = v;
        }
    }
    __syncthreads();

    int tx = tid & 15, ty = tid >> 4;
    int c0 = tx * 4, n0 = ty * 4;
    float acc[3][4][4] = {};

    #pragma unroll 2
    for (int k = 0; k < 64; k++) {
        float4 w0 = *(float4*)&sW[k * 64 + c0];
        float4 w1 = *(float4*)&sW[4096 + k * 64 + c0];
        float4 w2 = *(float4*)&sW[8192 + k * 64 + c0];
        float a[4];
        #pragma unroll
        for (int j = 0; j < 4; j++) a[j] = sIn[(n0 + j) * INPAD + k];
        #pragma unroll
        for (int j = 0; j < 4; j++) {
            acc[0][j][0] = fmaf(a[j], w0.x, acc[0][j][0]);
            acc[0][j][1] = fmaf(a[j], w0.y, acc[0][j][1]);
            acc[0][j][2] = fmaf(a[j], w0.z, acc[0][j][2]);
            acc[0][j][3] = fmaf(a[j], w0.w, acc[0][j][3]);
            acc[1][j][0] = fmaf(a[j], w1.x, acc[1][j][0]);
            acc[1][j][1] = fmaf(a[j], w1.y, acc[1][j][1]);
            acc[1][j][2] = fmaf(a[j], w1.z, acc[1][j][2]);
            acc[1][j][3] = fmaf(a[j], w1.w, acc[1][j][3]);
            acc[2][j][0] = fmaf(a[j], w2.x, acc[2][j][0]);
            acc[2][j][1] = fmaf(a[j], w2.y, acc[2][j][1]);
            acc[2][j][2] = fmaf(a[j], w2.z, acc[2][j][2]);
            acc[2][j][3] = fmaf(a[j], w2.w, acc[2][j][3]);
        }
    }

    float4 bv = *(const float4*)&bias2[c0];
    #pragma unroll
    for (int j = 0; j < 4; j++) {
        int node = nbase + n0 + j;
        if (node >= NN) break;
        *(float4*)&oAB[node * 128 + c0] =
            make_float4(acc[0][j][0], acc[0][j][1], acc[0][j][2], acc[0][j][3]);
        *(float4*)&oAB[node * 128 + 64 + c0] =
            make_float4(acc[1][j][0], acc[1][j][1], acc[1][j][2], acc[1][j][3]);
        *(float4*)&o2[node * 64 + c0] =
            make_float4(acc[2][j][0] + bv.x, acc[2][j][1] + bv.y,
                        acc[2][j][2] + bv.z, acc[2][j][3] + bv.w);
    }
}

// conv1 front: blocks [0, GEMM_GRID) gemm (mode 0); trailing blocks: degree hist.
__global__ __launch_bounds__(256)
void k_conv1_front(const float* __restrict__ x,
                   const float* __restrict__ W0,
                   const float* __restrict__ W1,
                   const float* __restrict__ W2,
                   const float* __restrict__ bias2,
                   const float* __restrict__ Wn,
                   const float* __restrict__ bn,
                   float* __restrict__ oAB,
                   float* __restrict__ o2,
                   const int* __restrict__ ei) {
    if (blockIdx.x < GEMM_GRID) {
        gemm_body(blockIdx.x, x, W0, W1, W2, bias2, Wn, bn, oAB, o2, 0);
    } else {
        int e = (blockIdx.x - GEMM_GRID) * blockDim.x + threadIdx.x;
        if (e < NE) atomicAdd(&g_deg[ei[NE + e]], 1);
    }
}

// conv2 node-side GEMM (mode 1)
__global__ __launch_bounds__(256)
void k_gemm3(const float* __restrict__ in,
             const float* __restrict__ W0,
             const float* __restrict__ W1,
             const float* __restrict__ W2,
             const float* __restrict__ bias2,
             float* __restrict__ oAB,
             float* __restrict__ o2) {
    gemm_body(blockIdx.x, in, W0, W1, W2, bias2, nullptr, nullptr, oAB, o2, 1);
}

// ---------------------------------------------------------------------------
// conv1 gather: one warp per dst node.
// Edge records staged 32-at-a-time with ONE coalesced load, then shuffle-
// broadcast per edge (kills the per-edge uniform LDG).
// ---------------------------------------------------------------------------
__global__ __launch_bounds__(256, 6)
void k_gather1(const float* __restrict__ We,
               const float* __restrict__ be,
               const float* __restrict__ W1e) {
    __shared__ float  sWe0[32], sWe1[32], sbe[32];
    __shared__ float2 sW1e[32 * 32];
    int tid = threadIdx.x;
    if (tid < 32) { sWe0[tid] = We[tid]; sWe1[tid] = We[32 + tid]; sbe[tid] = be[tid]; }
    for (int i = tid; i < 1024; i += blockDim.x)
        sW1e[i] = ((const float2*)W1e)[i];
    __syncthreads();

    int lane = tid & 31;
    int node = (blockIdx.x * blockDim.x + tid) >> 5;
    if (node >= NN) return;
    int s0 = g_off[node], s1 = g_off[node + 1];
    const float2* mm2 = (const float2*)g_mm;

    float we0 = sWe0[lane], we1 = sWe1[lane], beL = sbe[lane];
    float  ev = 0.f;
    float2 ms = make_float2(0.f, 0.f);

    for (int base = s0; base < s1; base += 32) {
        int cnt = min(32, s1 - base);
        uint4 d = make_uint4(0u, 0u, 0u, 0u);
        if (base + lane < s1) d = __ldg(&g_csr_ed[base + lane]);

        int k = 0;
        for (; k + 4 <= cnt; k += 4) {
            unsigned o0 = __shfl_sync(FULL, d.x, k);
            unsigned o1 = __shfl_sync(FULL, d.x, k + 1);
            unsigned o2 = __shfl_sync(FULL, d.x, k + 2);
            unsigned o3 = __shfl_sync(FULL, d.x, k + 3);
            float2 v0 = __ldg(&mm2[o0 + lane]);
            float2 v1 = __ldg(&mm2[o1 + lane]);
            float2 v2 = __ldg(&mm2[o2 + lane]);
            float2 v3 = __ldg(&mm2[o3 + lane]);
            float a0x = __uint_as_float(__shfl_sync(FULL, d.y, k));
            float a0y = __uint_as_float(__shfl_sync(FULL, d.z, k));
            float a1x = __uint_as_float(__shfl_sync(FULL, d.y, k + 1));
            float a1y = __uint_as_float(__shfl_sync(FULL, d.z, k + 1));
            float a2x = __uint_as_float(__shfl_sync(FULL, d.y, k + 2));
            float a2y = __uint_as_float(__shfl_sync(FULL, d.z, k + 2));
            float a3x = __uint_as_float(__shfl_sync(FULL, d.y, k + 3));
            float a3y = __uint_as_float(__shfl_sync(FULL, d.z, k + 3));
            ev += fmaxf(fmaf(a0x, we0, fmaf(a0y, we1, beL)), 0.f);
            ev += fmaxf(fmaf(a1x, we0, fmaf(a1y, we1, beL)), 0.f);
            ev += fmaxf(fmaf(a2x, we0, fmaf(a2y, we1, beL)), 0.f);
            ev += fmaxf(fmaf(a3x, we0, fmaf(a3y, we1, beL)), 0.f);
            ms.x += (v0.x + v1.x) + (v2.x + v3.x);
            ms.y += (v0.y + v1.y) + (v2.y + v3.y);
        }
        for (; k < cnt; k++) {
            unsigned off = __shfl_sync(FULL, d.x, k);
            float ax = __uint_as_float(__shfl_sync(FULL, d.y, k));
            float ay = __uint_as_float(__shfl_sync(FULL, d.z, k));
            float2 v = __ldg(&mm2[off + lane]);
            ev += fmaxf(fmaf(ax, we0, fmaf(ay, we1, beL)), 0.f);
            ms.x += v.x; ms.y += v.y;
        }
    }

    float2 acc = make_float2(0.f, 0.f);
    #pragma unroll
    for (int k = 0; k < 32; k++) {
        float ek = __shfl_sync(FULL, ev, k);
        float2 w = sW1e[k * 32 + lane];
        acc.x = fmaf(ek, w.x, acc.x);
        acc.y = fmaf(ek, w.y, acc.y);
    }
    float2 r = *(const float2*)&g_r1[node * 64 + 2 * lane];
    *(float2*)&g_hpre[node * 64 + 2 * lane] =
        make_float2(r.x + ms.x + acc.x, r.y + ms.y + acc.y);
}

// ---------------------------------------------------------------------------
// conv2 gather + readout: one warp per dst node; staged records + shuffle.
// ---------------------------------------------------------------------------
__global__ __launch_bounds__(256, 6)
void k_gather2(const float* __restrict__ Wc,
               const float* __restrict__ bc,
               float* __restrict__ out) {
    int tid  = threadIdx.x;
    int lane = tid & 31;
    int node = (blockIdx.x * blockDim.x + tid) >> 5;
    if (node >= NN) return;
    int s0 = g_off[node], s1 = g_off[node + 1];
    const float2* pp2 = (const float2*)g_pp;

    float2 mx = make_float2(-CUDART_INF_F, -CUDART_INF_F);
    for (int base = s0; base < s1; base += 32) {
        int cnt = min(32, s1 - base);
        unsigned dx = 0u;
        if (base + lane < s1) dx = __ldg(&g_csr_ed[base + lane]).x;

        int k = 0;
        for (; k + 4 <= cnt; k += 4) {
            unsigned o0 = __shfl_sync(FULL, dx, k);
            unsigned o1 = __shfl_sync(FULL, dx, k + 1);
            unsigned o2 = __shfl_sync(FULL, dx, k + 2);
            unsigned o3 = __shfl_sync(FULL, dx, k + 3);
            float2 v0 = __ldg(&pp2[o0 + lane]);
            float2 v1 = __ldg(&pp2[o1 + lane]);
            float2 v2 = __ldg(&pp2[o2 + lane]);
            float2 v3 = __ldg(&pp2[o3 + lane]);
            mx.x = fmaxf(mx.x, fmaxf(fmaxf(v0.x, v1.x), fmaxf(v2.x, v3.x)));
            mx.y = fmaxf(mx.y, fmaxf(fmaxf(v0.y, v1.y), fmaxf(v2.y, v3.y)));
        }
        for (; k < cnt; k++) {
            unsigned off = __shfl_sync(FULL, dx, k);
            float2 v = __ldg(&pp2[off + lane]);
            mx.x = fmaxf(mx.x, v.x);
            mx.y = fmaxf(mx.y, v.y);
        }
    }
    if (s1 == s0) mx = make_float2(0.f, 0.f);

    float2 r = *(const float2*)&g_r2[node * 64 + 2 * lane];
    float h0 = fmaxf(mx.x + r.x, 0.f);
    float h1 = fmaxf(mx.y + r.y, 0.f);
    float p = fmaf(h0, __ldg(&Wc[2 * lane]), h1 * __ldg(&Wc[2 * lane + 1]));
    #pragma unroll
    for (int o = 16; o > 0; o >>= 1) p += __shfl_xor_sync(FULL, p, o);
    if (lane == 0) out[node] = tanhf(p + __ldg(bc)) * 5.0f;
}

// ---------------------------------------------------------------------------
// launch
// ---------------------------------------------------------------------------
extern "C" void kernel_launch(void* const* d_in, const int* in_sizes, int n_in,
                              void* d_out, int out_size) {
    const float* x      = (const float*)d_in[0];
    const int*   ei     = (const int*)  d_in[1];
    const float* ea     = (const float*)d_in[2];
    const int*   et     = (const int*)  d_in[3];
    const float* Wn     = (const float*)d_in[4];
    const float* bn     = (const float*)d_in[5];
    const float* We     = (const float*)d_in[6];
    const float* be     = (const float*)d_in[7];
    const float* W1_rel = (const float*)d_in[8];
    const float* W1_edge= (const float*)d_in[9];
    const float* W1_root= (const float*)d_in[10];
    const float* b1     = (const float*)d_in[11];
    const float* W2_rel = (const float*)d_in[12];
    const float* W2_root= (const float*)d_in[13];
    const float* b2     = (const float*)d_in[14];
    const float* Wc     = (const float*)d_in[15];
    const float* bc     = (const float*)d_in[16];
    float* out          = (float*)d_out;

    float *pmm, *ppp, *pr1, *phpre, *pr2;
    int* pdeg;
    cudaGetSymbolAddress((void**)&pmm,   g_mm);
    cudaGetSymbolAddress((void**)&ppp,   g_pp);
    cudaGetSymbolAddress((void**)&pr1,   g_r1);
    cudaGetSymbolAddress((void**)&phpre, g_hpre);
    cudaGetSymbolAddress((void**)&pr2,   g_r2);
    cudaGetSymbolAddress((void**)&pdeg,  g_deg);

    static const int SMEM = (3 * 4096 + NPB * INPAD) * sizeof(float);
    cudaFuncSetAttribute(k_conv1_front, cudaFuncAttributeMaxDynamicSharedMemorySize, SMEM);
    cudaFuncSetAttribute(k_gemm3,       cudaFuncAttributeMaxDynamicSharedMemorySize, SMEM);

    const int edgeBlocks     = (NE + 255) / 256;
    const int nodeWarpBlocks = (NN * 32 + 255) / 256;

    cudaMemsetAsync(pdeg, 0, NN * sizeof(int));

    // conv1 node-side GEMMs (embed fused) + degree histogram in tail blocks
    k_conv1_front<<<GEMM_GRID + edgeBlocks, 256, SMEM>>>(
        x, W1_rel, W1_rel + 4096, W1_root, b1, Wn, bn, pmm, pr1, ei);

    // CSR offsets + fill
    k_scan<<<1, 1024>>>();
    k_fill<<<edgeBlocks, 256>>>(ei, ea, et);

    // conv1 gather (sum) + edge-feature fold
    k_gather1<<<nodeWarpBlocks, 256>>>(We, be, W1_edge);

    // conv2 node-side: h = relu(hpre) fused; pp table + r2
    k_gemm3<<<GEMM_GRID, 256, SMEM>>>(phpre, W2_rel, W2_rel + 4096, W2_root, b2,
                                      ppp, pr2);

    // conv2 gather (max) + readout fused
    k_gather2<<<nodeWarpBlocks, 256>>>(Wc, bc, out);
}